// round 7
// baseline (speedup 1.0000x reference)
#include <cuda_runtime.h>
#include <cuda_bf16.h>
#include <math.h>

#define FULLMASK 0xFFFFFFFFu

// Problem constants (fixed by the dataset)
#define NMAX   16384
#define INCH   128
#define SDIM   4
#define PDIM   64
#define OUTCH  128
#define KNN    50
#define NPER   4096   // nodes per segment (16384 / 4 splits)
#define CAP    128    // pass-2 collection buffer per query
#define QPW    4      // queries per warp in k2

// ---------------- device scratch (no allocation allowed) ----------------
__device__ float g_space[NMAX * SDIM];
__device__ float g_prop [NMAX * PDIM];
__device__ int   g_idx  [NMAX * KNN];
__device__ float g_w    [NMAX * KNN];   // exp(-10*d2), precomputed for k3

// Bit-exact replication of reference arithmetic (do not touch):
__device__ __forceinline__ float xla_sq4(float4 c) {
    return __fadd_rn(__fadd_rn(__fadd_rn(__fmul_rn(c.x, c.x), __fmul_rn(c.y, c.y)),
                               __fmul_rn(c.z, c.z)),
                     __fmul_rn(c.w, c.w));
}
__device__ __forceinline__ float cublas_dot4(float4 a, float4 b) {
    return __fmaf_rn(a.w, b.w, __fmaf_rn(a.z, b.z, __fmaf_rn(a.y, b.y, __fmul_rn(a.x, b.x))));
}
__device__ __forceinline__ float d2f(float4 cq, float sqq, float4 cj, float sqj) {
    const float dot = cublas_dot4(cq, cj);
    const float t   = __fadd_rn(sqq, sqj);
    return fmaxf(__fadd_rn(t, __fmul_rn(-2.0f, dot)), 0.0f);
}

// ---------------- K1: space = x@Ws + bs ; prop = x@Wp + bp ----------------
// 64 nodes/block, 256 threads (round-5 config, 22.4us measured).
__global__ __launch_bounds__(256) void k1_project(
        const float* __restrict__ x,
        const float* __restrict__ Ws, const float* __restrict__ bs,
        const float* __restrict__ Wp, const float* __restrict__ bp,
        float* __restrict__ out, int N) {
    __shared__ __align__(16) float sx [64 * INCH];        // 32 KB
    __shared__ __align__(16) float sWp[INCH * PDIM];      // 32 KB
    __shared__ float sWs[INCH * SDIM];                    //  2 KB
    const int tid = threadIdx.x;
    const int base = blockIdx.x * 64;

    for (int i = tid * 4; i < 64 * INCH; i += 1024)
        *(float4*)&sx[i] = *(const float4*)&x[(size_t)base * INCH + i];
    for (int i = tid * 4; i < INCH * PDIM; i += 1024)
        *(float4*)&sWp[i] = *(const float4*)&Wp[i];
    for (int i = tid; i < INCH * SDIM; i += 256) sWs[i] = Ws[i];
    __syncthreads();

    // ---- prop: register tile 4 nodes x 4 channels ----
    {
        const int cg = (tid & 15) * 4;          // c0
        const int ng = (tid >> 4) * 4;          // n0
        float acc[4][4];
        #pragma unroll
        for (int i = 0; i < 4; i++) {
            const float4 b4 = *(const float4*)&bp[cg];
            acc[i][0] = b4.x; acc[i][1] = b4.y; acc[i][2] = b4.z; acc[i][3] = b4.w;
        }
        for (int kk = 0; kk < INCH; kk += 4) {
            float4 xv[4];
            #pragma unroll
            for (int i = 0; i < 4; i++) xv[i] = *(const float4*)&sx[(ng + i) * INCH + kk];
            #pragma unroll
            for (int q = 0; q < 4; q++) {
                const float4 w4 = *(const float4*)&sWp[(kk + q) * PDIM + cg];
                #pragma unroll
                for (int i = 0; i < 4; i++) {
                    const float xs = (q == 0) ? xv[i].x : (q == 1) ? xv[i].y
                                   : (q == 2) ? xv[i].z : xv[i].w;
                    acc[i][0] = __fmaf_rn(xs, w4.x, acc[i][0]);
                    acc[i][1] = __fmaf_rn(xs, w4.y, acc[i][1]);
                    acc[i][2] = __fmaf_rn(xs, w4.z, acc[i][2]);
                    acc[i][3] = __fmaf_rn(xs, w4.w, acc[i][3]);
                }
            }
        }
        #pragma unroll
        for (int i = 0; i < 4; i++) {
            float4 r; r.x = acc[i][0]; r.y = acc[i][1]; r.z = acc[i][2]; r.w = acc[i][3];
            *(float4*)&g_prop[(size_t)(base + ng + i) * PDIM + cg] = r;
        }
    }

    // ---- space: exact sliced1x4 chain, one thread per (node, cs) ----
    {
        const int node = tid >> 2, cs = tid & 3;
        const float* xr = &sx[node * INCH];
        float s[4];
        #pragma unroll
        for (int sl = 0; sl < 4; sl++) {
            float acc = 0.0f;
            const int k0 = sl * 32;
            #pragma unroll
            for (int kk = 0; kk < 32; kk++)
                acc = __fmaf_rn(xr[k0 + kk], sWs[(k0 + kk) * SDIM + cs], acc);
            s[sl] = acc;
        }
        const float g = __fadd_rn(__fadd_rn(__fadd_rn(s[0], s[1]), s[2]), s[3]);
        const float v = __fadd_rn(g, bs[cs]);
        const int gn = base + node;
        g_space[(size_t)gn * SDIM + cs] = v;
        out[(size_t)N * 228 + (size_t)gn * SDIM + cs] = v;   // space output region
    }
}

// ---------------- K2: exact KNN via threshold-bound + compaction ----------------
// 256 threads = 8 warps; warp handles QPW=4 queries; 32 queries/block.
// Dynamic smem: coords float4[4096] 64KB | sq float[4096] 16KB
//             | vals u32[32][CAP] 16KB | idxs u16[32][CAP] 8KB   => 104KB, 2 CTAs/SM
#define K2_SMEM (NPER*16 + NPER*4 + 32*CAP*4 + 32*CAP*2)

__device__ __forceinline__ void k2_write(unsigned vbits, unsigned j, int rank, int gq,
                                         int segBase, float* __restrict__ out, int N) {
    const float v = __uint_as_float(vbits);
    const int gi = segBase + (int)j;
    g_idx[(size_t)gq * KNN + rank] = gi;
    g_w  [(size_t)gq * KNN + rank] = expf(-10.0f * v);
    out[(size_t)N * 128 + (size_t)gq * KNN + rank] = (float)gi;  // neighbor_idx region
    out[(size_t)N * 178 + (size_t)gq * KNN + rank] = v;          // distsq region
}

// 50th smallest (rank 49) of the 64 per-lane-top-2 subset values.
__device__ __forceinline__ float select49_64(const unsigned* __restrict__ vals,
                                             const unsigned short* __restrict__ idxs,
                                             float a0, float a1, int lane) {
    const unsigned long long k0 =
        ((unsigned long long)__float_as_uint(a0) << 16) | (unsigned)(lane * 2 + 0);
    const unsigned long long k1 =
        ((unsigned long long)__float_as_uint(a1) << 16) | (unsigned)(lane * 2 + 1);
    int r0 = 0, r1 = 0;
    #pragma unroll 8
    for (int n = 0; n < 64; n++) {
        const unsigned long long u = ((unsigned long long)vals[n] << 16) | idxs[n];
        r0 += (u < k0); r1 += (u < k1);
    }
    const bool h = (r0 == 49) || (r1 == 49);
    const float vh = (r0 == 49) ? a0 : a1;
    const unsigned m = __ballot_sync(FULLMASK, h);
    return __shfl_sync(FULLMASK, vh, __ffs(m) - 1);
}

__device__ void k2_finalize(const unsigned* __restrict__ vals,
                            const unsigned short* __restrict__ idxs,
                            unsigned cnt, int gq,
                            float4 cq, float sqq, int segBase, int lane,
                            const float4* __restrict__ sC, const float* __restrict__ sSq,
                            float* __restrict__ out, int N) {
    if (cnt >= KNN && cnt <= CAP) {
        for (int m = lane; m < (int)cnt; m += 32) {
            const unsigned long long key =
                ((unsigned long long)vals[m] << 16) | idxs[m];
            int rank = 0;
            for (int n = 0; n < (int)cnt; n++) {
                const unsigned long long u = ((unsigned long long)vals[n] << 16) | idxs[n];
                rank += (u < key);
            }
            if (rank < KNN) k2_write(vals[m], idxs[m], rank, gq, segBase, out, N);
        }
    } else {
        // Exact deterministic fallback (practically never taken).
        long long prev = -1;
        for (int r = 0; r < KNN; r++) {
            unsigned long long best = ~0ull;
            for (int j = lane; j < NPER; j += 32) {
                const float v = d2f(cq, sqq, sC[j], sSq[j]);
                const unsigned long long key =
                    ((unsigned long long)__float_as_uint(v) << 16) | (unsigned)j;
                if ((long long)key > prev && key < best) best = key;
            }
            #pragma unroll
            for (int off = 16; off; off >>= 1) {
                const unsigned long long o = __shfl_xor_sync(FULLMASK, best, off);
                if (o < best) best = o;
            }
            if (lane == 0)
                k2_write((unsigned)(best >> 16), (unsigned)(best & 0xFFFFull),
                         r, gq, segBase, out, N);
            prev = (long long)best;
        }
    }
}

__global__ __launch_bounds__(256) void k2_knn(float* __restrict__ out, int N) {
    extern __shared__ unsigned char dsm[];
    float4*         sC   = (float4*)dsm;                              // 64 KB
    float*          sSq  = (float*)(dsm + NPER * 16);                 // 16 KB
    unsigned*       sVal = (unsigned*)(dsm + NPER * 20);              // 16 KB
    unsigned short* sIdx = (unsigned short*)(dsm + NPER * 20 + 32 * CAP * 4); // 8 KB
    __shared__ unsigned scnt[32];

    const int tid = threadIdx.x;
    const int w = tid >> 5, lane = tid & 31;
    const int qBase = blockIdx.x * 32;
    const int segBase = qBase & ~(NPER - 1);

    for (int j = tid; j < NPER; j += 256) {
        const float4 c = *(const float4*)&g_space[(size_t)(segBase + j) * 4];
        sC[j] = c;
        sSq[j] = xla_sq4(c);
    }
    if (tid < 32) scnt[tid] = 0;
    __syncthreads();

    const int qw = w * QPW;               // first query (block-local) of this warp
    float4 cq[QPW]; float sq[QPW];
    #pragma unroll
    for (int i = 0; i < QPW; i++) {
        const int ql = qBase - segBase + qw + i;
        cq[i] = sC[ql]; sq[i] = sSq[ql];
    }

    // ---- Pass 1: per-lane top-2 for all QPW queries ----
    float a0[QPW], a1[QPW];
    #pragma unroll
    for (int i = 0; i < QPW; i++) { a0[i] = INFINITY; a1[i] = INFINITY; }
    for (int j = lane; j < NPER; j += 32) {
        const float4 cj = sC[j]; const float sj = sSq[j];
        #pragma unroll
        for (int i = 0; i < QPW; i++) {
            const float v = d2f(cq[i], sq[i], cj, sj);
            a1[i] = fminf(a1[i], fmaxf(a0[i], v));
            a0[i] = fminf(a0[i], v);
        }
    }

    // ---- Threshold per query = 50th smallest of the 64 subset values ----
    float T[QPW];
    #pragma unroll
    for (int i = 0; i < QPW; i++) {
        unsigned*       bv = sVal + (size_t)(qw + i) * CAP;
        unsigned short* bi = sIdx + (size_t)(qw + i) * CAP;
        bv[lane * 2 + 0] = __float_as_uint(a0[i]);
        bi[lane * 2 + 0] = (unsigned short)(lane * 2 + 0);
        bv[lane * 2 + 1] = __float_as_uint(a1[i]);
        bi[lane * 2 + 1] = (unsigned short)(lane * 2 + 1);
        __syncwarp();
        T[i] = select49_64(bv, bi, a0[i], a1[i], lane);
        __syncwarp();
    }

    // ---- Pass 2: compaction of all d2 <= T via smem atomic counters ----
    for (int j = lane; j < NPER; j += 32) {
        const float4 cj = sC[j]; const float sj = sSq[j];
        #pragma unroll
        for (int i = 0; i < QPW; i++) {
            const float v = d2f(cq[i], sq[i], cj, sj);
            if (v <= T[i]) {
                const unsigned p = atomicAdd(&scnt[qw + i], 1u);
                if (p < CAP) {
                    sVal[(size_t)(qw + i) * CAP + p] = __float_as_uint(v);
                    sIdx[(size_t)(qw + i) * CAP + p] = (unsigned short)j;
                }
            }
        }
    }
    __syncwarp();

    // ---- Final exact rank-sort + writes ----
    #pragma unroll
    for (int i = 0; i < QPW; i++) {
        k2_finalize(sVal + (size_t)(qw + i) * CAP, sIdx + (size_t)(qw + i) * CAP,
                    scnt[qw + i], qBase + qw + i,
                    cq[i], sq[i], segBase, lane, sC, sSq, out, N);
    }
}

// ---------------- K3: gather + mean/max + output GEMM + relu ----------------
// 32 nodes/block, 256 threads; gather runs 4 nodes concurrently.
__global__ __launch_bounds__(256) void k3_aggregate(
        const float* __restrict__ x,
        const float* __restrict__ Wo, const float* __restrict__ bo,
        float* __restrict__ out) {
    __shared__ __align__(16) float feat[32][2 * PDIM + INCH];   // 32 KB
    __shared__ float swarr[32 * KNN];                            // 6.4 KB
    __shared__ int   sgidx[32 * KNN];                            // 6.4 KB

    const int tid = threadIdx.x;
    const int base = blockIdx.x * 32;

    for (int i = tid * 4; i < 32 * INCH; i += 1024) {
        const int node = i >> 7, c = i & 127;
        *(float4*)&feat[node][c] = *(const float4*)&x[(size_t)(base + node) * INCH + c];
    }
    for (int i = tid; i < 32 * KNN; i += 256) {
        swarr[i] = g_w  [(size_t)base * KNN + i];
        sgidx[i] = g_idx[(size_t)base * KNN + i];
    }
    __syncthreads();

    {
        const int ns = tid >> 6, c = tid & 63;
        for (int nn = ns; nn < 32; nn += 4) {
            const float* wr = &swarr[nn * KNN];
            const int*   ir = &sgidx[nn * KNN];
            float acc = 0.0f, mx = -INFINITY;
            #pragma unroll 5
            for (int r = 0; r < KNN; r++) {
                const float v = g_prop[(size_t)ir[r] * PDIM + c] * wr[r];
                acc += v; mx = fmaxf(mx, v);
            }
            feat[nn][INCH + c]        = acc * (1.0f / (float)KNN);
            feat[nn][INCH + PDIM + c] = mx;
        }
    }
    __syncthreads();

    const int c = tid & 127;
    const int t0 = (tid >> 7) * 16;
    float acc[16];
    #pragma unroll
    for (int t = 0; t < 16; t++) acc[t] = bo[c];
    for (int kk = 0; kk < 2 * PDIM + INCH; kk += 4) {
        const float w0 = Wo[(size_t)(kk + 0) * OUTCH + c];
        const float w1 = Wo[(size_t)(kk + 1) * OUTCH + c];
        const float w2 = Wo[(size_t)(kk + 2) * OUTCH + c];
        const float w3 = Wo[(size_t)(kk + 3) * OUTCH + c];
        #pragma unroll
        for (int t = 0; t < 16; t++) {
            const float4 f = *(const float4*)&feat[t0 + t][kk];
            acc[t] = __fmaf_rn(f.x, w0, acc[t]);
            acc[t] = __fmaf_rn(f.y, w1, acc[t]);
            acc[t] = __fmaf_rn(f.z, w2, acc[t]);
            acc[t] = __fmaf_rn(f.w, w3, acc[t]);
        }
    }
    #pragma unroll
    for (int t = 0; t < 16; t++)
        out[(size_t)(base + t0 + t) * OUTCH + c] = fmaxf(acc[t], 0.0f);
}

// ---------------- launch ----------------
extern "C" void kernel_launch(void* const* d_in, const int* in_sizes, int n_in,
                              void* d_out, int out_size) {
    const float* x  = (const float*)d_in[0];
    const float* Ws = (const float*)d_in[2];
    const float* bs = (const float*)d_in[3];
    const float* Wp = (const float*)d_in[4];
    const float* bp = (const float*)d_in[5];
    const float* Wo = (const float*)d_in[6];
    const float* bo = (const float*)d_in[7];

    const int N = in_sizes[0] / INCH;   // 16384
    float* out = (float*)d_out;

    k1_project<<<N / 64, 256>>>(x, Ws, bs, Wp, bp, out, N);

    cudaFuncSetAttribute(k2_knn, cudaFuncAttributeMaxDynamicSharedMemorySize, K2_SMEM);
    k2_knn<<<N / 32, 256, K2_SMEM>>>(out, N);

    k3_aggregate<<<N / 32, 256>>>(x, Wo, bo, out);

    (void)n_in; (void)in_sizes; (void)out_size;
}

// round 8
// speedup vs baseline: 1.1341x; 1.1341x over previous
#include <cuda_runtime.h>
#include <cuda_bf16.h>
#include <math.h>

#define FULLMASK 0xFFFFFFFFu

// Problem constants (fixed by the dataset)
#define NMAX   16384
#define INCH   128
#define SDIM   4
#define PDIM   64
#define OUTCH  128
#define KNN    50
#define NPER   4096   // nodes per segment (16384 / 4 splits)
#define CAP    128    // pass-2 collection buffer per query

// ---------------- device scratch (no allocation allowed) ----------------
__device__ float g_space[NMAX * SDIM];
__device__ float g_prop [NMAX * PDIM];
__device__ int   g_idx  [NMAX * KNN];
__device__ float g_w    [NMAX * KNN];   // exp(-10*d2), precomputed for k3

// Bit-exact replication of reference arithmetic (do not touch):
__device__ __forceinline__ float xla_sq4(float4 c) {
    return __fadd_rn(__fadd_rn(__fadd_rn(__fmul_rn(c.x, c.x), __fmul_rn(c.y, c.y)),
                               __fmul_rn(c.z, c.z)),
                     __fmul_rn(c.w, c.w));
}
__device__ __forceinline__ float cublas_dot4(float4 a, float4 b) {
    return __fmaf_rn(a.w, b.w, __fmaf_rn(a.z, b.z, __fmaf_rn(a.y, b.y, __fmul_rn(a.x, b.x))));
}
__device__ __forceinline__ float d2f(float4 cq, float sqq, float4 cj, float sqj) {
    const float dot = cublas_dot4(cq, cj);
    const float t   = __fadd_rn(sqq, sqj);
    return fmaxf(__fadd_rn(t, __fmul_rn(-2.0f, dot)), 0.0f);
}

// ---------------- K1: space = x@Ws + bs ; prop = x@Wp + bp ----------------
// 64 nodes/block, 256 threads (measured best: 22.4us).
__global__ __launch_bounds__(256) void k1_project(
        const float* __restrict__ x,
        const float* __restrict__ Ws, const float* __restrict__ bs,
        const float* __restrict__ Wp, const float* __restrict__ bp,
        float* __restrict__ out, int N) {
    __shared__ __align__(16) float sx [64 * INCH];        // 32 KB
    __shared__ __align__(16) float sWp[INCH * PDIM];      // 32 KB
    __shared__ float sWs[INCH * SDIM];                    //  2 KB
    const int tid = threadIdx.x;
    const int base = blockIdx.x * 64;

    for (int i = tid * 4; i < 64 * INCH; i += 1024)
        *(float4*)&sx[i] = *(const float4*)&x[(size_t)base * INCH + i];
    for (int i = tid * 4; i < INCH * PDIM; i += 1024)
        *(float4*)&sWp[i] = *(const float4*)&Wp[i];
    for (int i = tid; i < INCH * SDIM; i += 256) sWs[i] = Ws[i];
    __syncthreads();

    // ---- prop: register tile 4 nodes x 4 channels ----
    {
        const int cg = (tid & 15) * 4;          // c0
        const int ng = (tid >> 4) * 4;          // n0
        float acc[4][4];
        #pragma unroll
        for (int i = 0; i < 4; i++) {
            const float4 b4 = *(const float4*)&bp[cg];
            acc[i][0] = b4.x; acc[i][1] = b4.y; acc[i][2] = b4.z; acc[i][3] = b4.w;
        }
        for (int kk = 0; kk < INCH; kk += 4) {
            float4 xv[4];
            #pragma unroll
            for (int i = 0; i < 4; i++) xv[i] = *(const float4*)&sx[(ng + i) * INCH + kk];
            #pragma unroll
            for (int q = 0; q < 4; q++) {
                const float4 w4 = *(const float4*)&sWp[(kk + q) * PDIM + cg];
                #pragma unroll
                for (int i = 0; i < 4; i++) {
                    const float xs = (q == 0) ? xv[i].x : (q == 1) ? xv[i].y
                                   : (q == 2) ? xv[i].z : xv[i].w;
                    acc[i][0] = __fmaf_rn(xs, w4.x, acc[i][0]);
                    acc[i][1] = __fmaf_rn(xs, w4.y, acc[i][1]);
                    acc[i][2] = __fmaf_rn(xs, w4.z, acc[i][2]);
                    acc[i][3] = __fmaf_rn(xs, w4.w, acc[i][3]);
                }
            }
        }
        #pragma unroll
        for (int i = 0; i < 4; i++) {
            float4 r; r.x = acc[i][0]; r.y = acc[i][1]; r.z = acc[i][2]; r.w = acc[i][3];
            *(float4*)&g_prop[(size_t)(base + ng + i) * PDIM + cg] = r;
        }
    }

    // ---- space: exact sliced1x4 chain, one thread per (node, cs) ----
    {
        const int node = tid >> 2, cs = tid & 3;
        const float* xr = &sx[node * INCH];
        float s[4];
        #pragma unroll
        for (int sl = 0; sl < 4; sl++) {
            float acc = 0.0f;
            const int k0 = sl * 32;
            #pragma unroll
            for (int kk = 0; kk < 32; kk++)
                acc = __fmaf_rn(xr[k0 + kk], sWs[(k0 + kk) * SDIM + cs], acc);
            s[sl] = acc;
        }
        const float g = __fadd_rn(__fadd_rn(__fadd_rn(s[0], s[1]), s[2]), s[3]);
        const float v = __fadd_rn(g, bs[cs]);
        const int gn = base + node;
        g_space[(size_t)gn * SDIM + cs] = v;
        out[(size_t)N * 228 + (size_t)gn * SDIM + cs] = v;   // space output region
    }
}

// ---------------- K2: exact KNN via threshold-bound + compaction ----------------
// Round-5 config (best measured) + 2-candidate ILP unroll in both sweeps.
// 256 threads = 8 warps; warp handles 2 queries; 16 queries/block; grid 1024.
// Dynamic smem: coords float4[4096] 64KB | sq float[4096] 16KB | buf u64[16][CAP] 16KB
#define K2_SMEM (NPER*16 + NPER*4 + 16*CAP*8)

__device__ __forceinline__ void k2_write(unsigned long long key, int rank, int gq,
                                         int segBase, float* __restrict__ out, int N) {
    const int j = (int)(key & 0xFFFFFFFFull);
    const float v = __uint_as_float((unsigned)(key >> 32));
    const int gi = segBase + j;
    g_idx[(size_t)gq * KNN + rank] = gi;
    g_w  [(size_t)gq * KNN + rank] = expf(-10.0f * v);
    out[(size_t)N * 128 + (size_t)gq * KNN + rank] = (float)gi;  // neighbor_idx region
    out[(size_t)N * 178 + (size_t)gq * KNN + rank] = v;          // distsq region
}

__device__ __forceinline__ float select49(const unsigned long long* __restrict__ buf,
                                          float a0, float a1, float a2, int lane) {
    const unsigned long long k0 = ((unsigned long long)__float_as_uint(a0) << 32) | (unsigned)(lane * 3 + 0);
    const unsigned long long k1 = ((unsigned long long)__float_as_uint(a1) << 32) | (unsigned)(lane * 3 + 1);
    const unsigned long long k2 = ((unsigned long long)__float_as_uint(a2) << 32) | (unsigned)(lane * 3 + 2);
    int r0 = 0, r1 = 0, r2 = 0;
    for (int n = 0; n < 96; n++) {
        const unsigned long long u = buf[n];
        r0 += (u < k0); r1 += (u < k1); r2 += (u < k2);
    }
    const bool h = (r0 == 49) || (r1 == 49) || (r2 == 49);
    const float vh = (r0 == 49) ? a0 : ((r1 == 49) ? a1 : a2);
    const unsigned m = __ballot_sync(FULLMASK, h);
    return __shfl_sync(FULLMASK, vh, __ffs(m) - 1);
}

__device__ void k2_finalize(const unsigned long long* __restrict__ buf, unsigned cnt, int gq,
                            float4 cq, float sqq, int segBase, int lane,
                            const float4* __restrict__ sC, const float* __restrict__ sSq,
                            float* __restrict__ out, int N) {
    if (cnt >= KNN && cnt <= CAP) {
        for (int m = lane; m < (int)cnt; m += 32) {
            const unsigned long long key = buf[m];
            int rank = 0;
            for (int n = 0; n < (int)cnt; n++) rank += (buf[n] < key);
            if (rank < KNN) k2_write(key, rank, gq, segBase, out, N);
        }
    } else {
        // Exact deterministic fallback (practically never taken).
        long long prev = -1;
        for (int r = 0; r < KNN; r++) {
            unsigned long long best = ~0ull;
            for (int j = lane; j < NPER; j += 32) {
                const float v = d2f(cq, sqq, sC[j], sSq[j]);
                const unsigned long long key =
                    ((unsigned long long)__float_as_uint(v) << 32) | (unsigned)j;
                if ((long long)key > prev && key < best) best = key;
            }
            #pragma unroll
            for (int off = 16; off; off >>= 1) {
                const unsigned long long o = __shfl_xor_sync(FULLMASK, best, off);
                if (o < best) best = o;
            }
            if (lane == 0) k2_write(best, r, gq, segBase, out, N);
            prev = (long long)best;
        }
    }
}

// top-3 update network (ascending a0<=a1<=a2)
#define TOP3_UPD(a0, a1, a2, v) do { \
    a2 = fminf(a2, fmaxf(a1, v)); a1 = fminf(a1, fmaxf(a0, v)); a0 = fminf(a0, v); \
} while (0)

__global__ __launch_bounds__(256) void k2_knn(float* __restrict__ out, int N) {
    extern __shared__ unsigned char dsm[];
    float4*             sC   = (float4*)dsm;                          // 64 KB
    float*              sSq  = (float*)(dsm + NPER * 16);             // 16 KB
    unsigned long long* sBuf = (unsigned long long*)(dsm + NPER * 20);// 16 KB
    __shared__ unsigned scnt[16];

    const int tid = threadIdx.x;
    const int w = tid >> 5, lane = tid & 31;
    const int qBase = blockIdx.x * 16;
    const int segBase = qBase & ~(NPER - 1);

    for (int j = tid; j < NPER; j += 256) {
        const float4 c = *(const float4*)&g_space[(size_t)(segBase + j) * 4];
        sC[j] = c;
        sSq[j] = xla_sq4(c);
    }
    if (tid < 16) scnt[tid] = 0;
    __syncthreads();

    const int q0 = qBase + 2 * w;
    const int ql = q0 - segBase;
    const float4 cq0 = sC[ql];     const float sq0 = sSq[ql];
    const float4 cq1 = sC[ql + 1]; const float sq1 = sSq[ql + 1];
    unsigned long long* buf0 = sBuf + (size_t)(2 * w) * CAP;
    unsigned long long* buf1 = buf0 + CAP;

    // ---- Pass 1: per-lane top-3, 2 candidates/iter with independent A/B chains ----
    float aA0 = INFINITY, aA1 = INFINITY, aA2 = INFINITY;   // q0, candidate stream A
    float aB0 = INFINITY, aB1 = INFINITY, aB2 = INFINITY;   // q0, candidate stream B
    float bA0 = INFINITY, bA1 = INFINITY, bA2 = INFINITY;   // q1, A
    float bB0 = INFINITY, bB1 = INFINITY, bB2 = INFINITY;   // q1, B
    for (int j = lane; j < NPER; j += 64) {
        const int j2 = j + 32;
        const float4 cjA = sC[j];  const float sjA = sSq[j];
        const float4 cjB = sC[j2]; const float sjB = sSq[j2];
        const float vA0 = d2f(cq0, sq0, cjA, sjA);
        const float vB0 = d2f(cq0, sq0, cjB, sjB);
        const float vA1 = d2f(cq1, sq1, cjA, sjA);
        const float vB1 = d2f(cq1, sq1, cjB, sjB);
        TOP3_UPD(aA0, aA1, aA2, vA0);
        TOP3_UPD(aB0, aB1, aB2, vB0);
        TOP3_UPD(bA0, bA1, bA2, vA1);
        TOP3_UPD(bB0, bB1, bB2, vB1);
    }
    // Merge A/B top-3 sets (exact 3 smallest of the union; set semantics ==
    // sequential processing, so per-lane top-3 values identical to round 5).
    float a0, a1, a2, b0, b1, b2;
    {
        const float u0 = fmaxf(aA0, aB0), t1 = fminf(aA1, aB1), c2 = fminf(aA2, aB2);
        a0 = fminf(aA0, aB0);
        a1 = fminf(u0, t1);
        a2 = fmaxf(fminf(u0, t1), fminf(fmaxf(u0, t1), c2));   // median(u0,t1,c2)
    }
    {
        const float u0 = fmaxf(bA0, bB0), t1 = fminf(bA1, bB1), c2 = fminf(bA2, bB2);
        b0 = fminf(bA0, bB0);
        b1 = fminf(u0, t1);
        b2 = fmaxf(fminf(u0, t1), fminf(fmaxf(u0, t1), c2));
    }

    // ---- Upper-bound threshold = 50th smallest of the 96 candidates ----
    buf0[lane * 3 + 0] = ((unsigned long long)__float_as_uint(a0) << 32) | (unsigned)(lane * 3 + 0);
    buf0[lane * 3 + 1] = ((unsigned long long)__float_as_uint(a1) << 32) | (unsigned)(lane * 3 + 1);
    buf0[lane * 3 + 2] = ((unsigned long long)__float_as_uint(a2) << 32) | (unsigned)(lane * 3 + 2);
    buf1[lane * 3 + 0] = ((unsigned long long)__float_as_uint(b0) << 32) | (unsigned)(lane * 3 + 0);
    buf1[lane * 3 + 1] = ((unsigned long long)__float_as_uint(b1) << 32) | (unsigned)(lane * 3 + 1);
    buf1[lane * 3 + 2] = ((unsigned long long)__float_as_uint(b2) << 32) | (unsigned)(lane * 3 + 2);
    __syncwarp();
    const float T0 = select49(buf0, a0, a1, a2, lane);
    const float T1 = select49(buf1, b0, b1, b2, lane);
    __syncwarp();

    // ---- Pass 2: compaction of all d2 <= T (atomic counters; order-free) ----
    unsigned* cnt0 = &scnt[2 * w];
    unsigned* cnt1 = &scnt[2 * w + 1];
    for (int j = lane; j < NPER; j += 64) {
        const int j2 = j + 32;
        const float4 cjA = sC[j];  const float sjA = sSq[j];
        const float4 cjB = sC[j2]; const float sjB = sSq[j2];
        const float vA0 = d2f(cq0, sq0, cjA, sjA);
        const float vB0 = d2f(cq0, sq0, cjB, sjB);
        const float vA1 = d2f(cq1, sq1, cjA, sjA);
        const float vB1 = d2f(cq1, sq1, cjB, sjB);
        if (vA0 <= T0) {
            const unsigned p = atomicAdd(cnt0, 1u);
            if (p < CAP) buf0[p] = ((unsigned long long)__float_as_uint(vA0) << 32) | (unsigned)j;
        }
        if (vB0 <= T0) {
            const unsigned p = atomicAdd(cnt0, 1u);
            if (p < CAP) buf0[p] = ((unsigned long long)__float_as_uint(vB0) << 32) | (unsigned)j2;
        }
        if (vA1 <= T1) {
            const unsigned p = atomicAdd(cnt1, 1u);
            if (p < CAP) buf1[p] = ((unsigned long long)__float_as_uint(vA1) << 32) | (unsigned)j;
        }
        if (vB1 <= T1) {
            const unsigned p = atomicAdd(cnt1, 1u);
            if (p < CAP) buf1[p] = ((unsigned long long)__float_as_uint(vB1) << 32) | (unsigned)j2;
        }
    }
    __syncwarp();

    // ---- Final exact rank-sort + writes ----
    k2_finalize(buf0, *cnt0, q0,     cq0, sq0, segBase, lane, sC, sSq, out, N);
    k2_finalize(buf1, *cnt1, q0 + 1, cq1, sq1, segBase, lane, sC, sSq, out, N);
}

// ---------------- K3: gather + mean/max + output GEMM + relu ----------------
// 32 nodes/block, 256 threads; gather runs 4 nodes concurrently.
__global__ __launch_bounds__(256) void k3_aggregate(
        const float* __restrict__ x,
        const float* __restrict__ Wo, const float* __restrict__ bo,
        float* __restrict__ out) {
    __shared__ __align__(16) float feat[32][2 * PDIM + INCH];   // 32 KB
    __shared__ float swarr[32 * KNN];                            // 6.4 KB
    __shared__ int   sgidx[32 * KNN];                            // 6.4 KB

    const int tid = threadIdx.x;
    const int base = blockIdx.x * 32;

    for (int i = tid * 4; i < 32 * INCH; i += 1024) {
        const int node = i >> 7, c = i & 127;
        *(float4*)&feat[node][c] = *(const float4*)&x[(size_t)(base + node) * INCH + c];
    }
    for (int i = tid; i < 32 * KNN; i += 256) {
        swarr[i] = g_w  [(size_t)base * KNN + i];
        sgidx[i] = g_idx[(size_t)base * KNN + i];
    }
    __syncthreads();

    {
        const int ns = tid >> 6, c = tid & 63;
        for (int nn = ns; nn < 32; nn += 4) {
            const float* wr = &swarr[nn * KNN];
            const int*   ir = &sgidx[nn * KNN];
            float acc = 0.0f, mx = -INFINITY;
            #pragma unroll 5
            for (int r = 0; r < KNN; r++) {
                const float v = g_prop[(size_t)ir[r] * PDIM + c] * wr[r];
                acc += v; mx = fmaxf(mx, v);
            }
            feat[nn][INCH + c]        = acc * (1.0f / (float)KNN);
            feat[nn][INCH + PDIM + c] = mx;
        }
    }
    __syncthreads();

    const int c = tid & 127;
    const int t0 = (tid >> 7) * 16;
    float acc[16];
    #pragma unroll
    for (int t = 0; t < 16; t++) acc[t] = bo[c];
    for (int kk = 0; kk < 2 * PDIM + INCH; kk += 4) {
        const float w0 = Wo[(size_t)(kk + 0) * OUTCH + c];
        const float w1 = Wo[(size_t)(kk + 1) * OUTCH + c];
        const float w2 = Wo[(size_t)(kk + 2) * OUTCH + c];
        const float w3 = Wo[(size_t)(kk + 3) * OUTCH + c];
        #pragma unroll
        for (int t = 0; t < 16; t++) {
            const float4 f = *(const float4*)&feat[t0 + t][kk];
            acc[t] = __fmaf_rn(f.x, w0, acc[t]);
            acc[t] = __fmaf_rn(f.y, w1, acc[t]);
            acc[t] = __fmaf_rn(f.z, w2, acc[t]);
            acc[t] = __fmaf_rn(f.w, w3, acc[t]);
        }
    }
    #pragma unroll
    for (int t = 0; t < 16; t++)
        out[(size_t)(base + t0 + t) * OUTCH + c] = fmaxf(acc[t], 0.0f);
}

// ---------------- launch ----------------
extern "C" void kernel_launch(void* const* d_in, const int* in_sizes, int n_in,
                              void* d_out, int out_size) {
    const float* x  = (const float*)d_in[0];
    const float* Ws = (const float*)d_in[2];
    const float* bs = (const float*)d_in[3];
    const float* Wp = (const float*)d_in[4];
    const float* bp = (const float*)d_in[5];
    const float* Wo = (const float*)d_in[6];
    const float* bo = (const float*)d_in[7];

    const int N = in_sizes[0] / INCH;   // 16384
    float* out = (float*)d_out;

    k1_project<<<N / 64, 256>>>(x, Ws, bs, Wp, bp, out, N);

    cudaFuncSetAttribute(k2_knn, cudaFuncAttributeMaxDynamicSharedMemorySize, K2_SMEM);
    k2_knn<<<N / 16, 256, K2_SMEM>>>(out, N);

    k3_aggregate<<<N / 32, 256>>>(x, Wo, bo, out);

    (void)n_in; (void)in_sizes; (void)out_size;
}